// round 15
// baseline (speedup 1.0000x reference)
#include <cuda_runtime.h>
#include <cstdint>
#include <math.h>

#define CCH   512
#define NTOK  4096
#define BATCH 8
#define NG    32
#define CPG   16

#define SBN ((size_t)NTOK * CCH)    // per-batch activation stride (elements)
#define SBS ((size_t)NTOK * NTOK)   // per-batch attention stride

// -------- scratch (device globals; referenced ONLY in device code) --------
__device__ __align__(16) uint16_t g_hh[(size_t)BATCH * NTOK * CCH];  // GN out, TRANSPOSED [b][n][c]
__device__ __align__(16) uint16_t g_qt[(size_t)BATCH * NTOK * CCH];  // Qt [b][n][c]
__device__ __align__(16) uint16_t g_kt[(size_t)BATCH * NTOK * CCH];  // Kt [b][n][c]
__device__ __align__(16) uint16_t g_v [(size_t)BATCH * CCH * NTOK];  // V  [b][c][n]
__device__ __align__(16) uint16_t g_wq[CCH * CCH];
__device__ __align__(16) uint16_t g_wk[CCH * CCH];
__device__ __align__(16) uint16_t g_wv[CCH * CCH];
__device__ float g_s[(size_t)BATCH * NTOK * NTOK];                   // logits fp32 [b][i][j]
__device__ __align__(16) uint16_t g_p[(size_t)BATCH * NTOK * NTOK]; // probs fp16 [b][i][j]

// pack two fp32 -> one fp16x2 word (lo = first arg, hi = second arg)
#define PACK_H2(dst, lo, hi)                                                  \
    asm("cvt.rn.f16x2.f32 %0, %1, %2;" : "=r"(dst) : "f"(hi), "f"(lo))

#define MMA_F16(c0, c1, c2, c3, a0, a1, a2, a3, b0, b1)                       \
    asm volatile("mma.sync.aligned.m16n8k16.row.col.f32.f16.f16.f32 "         \
                 "{%0,%1,%2,%3}, {%4,%5,%6,%7}, {%8,%9}, {%0,%1,%2,%3};"      \
                 : "+f"(c0), "+f"(c1), "+f"(c2), "+f"(c3)                     \
                 : "r"(a0), "r"(a1), "r"(a2), "r"(a3), "r"(b0), "r"(b1))

#define LDSM_X4(r0, r1, r2, r3, addr)                                         \
    asm volatile("ldmatrix.sync.aligned.m8n8.x4.shared.b16 {%0,%1,%2,%3}, [%4];" \
                 : "=r"(r0), "=r"(r1), "=r"(r2), "=r"(r3) : "r"(addr))

__device__ __forceinline__ uint32_t smem_u32(const void* p) {
    uint32_t a;
    asm("{ .reg .u64 t; cvta.to.shared.u64 t, %1; cvt.u32.u64 %0, t; }" : "=r"(a) : "l"(p));
    return a;
}

// ============================================================================
// Shared GEMM machinery: CTA 128x128x32(halves), 128 threads (2x2 warps),
// warp tile 64x64. Double-buffered static smem [2][128][40] uint16, register
// prefetch (8 x uint4), one __syncthreads per slab. Fragments via ldmatrix.x4.
// D[m][n] = sum_k A[m+m0][k] * B[n+n0][k]
// ============================================================================
#define LDHH 40                       // padded smem row (halves)
#define STAGEB (128 * LDHH * 2)       // stage size in bytes = 10240

#define DECL_ACC()                                                            \
    const int tid = threadIdx.x;                                              \
    const int wid = tid >> 5, lane = tid & 31;                                \
    const int wm = wid & 1, wn = wid >> 1;      /* 2 (M) x 2 (N) warps */     \
    const int g = lane >> 2, t = lane & 3;                                    \
    float acc[4][8][4];                                                       \
    _Pragma("unroll")                                                         \
    for (int mt = 0; mt < 4; mt++)                                            \
        _Pragma("unroll")                                                     \
        for (int nt = 0; nt < 8; nt++) {                                      \
            acc[mt][nt][0] = 0.f; acc[mt][nt][1] = 0.f;                       \
            acc[mt][nt][2] = 0.f; acc[mt][nt][3] = 0.f;                       \
        }

// ldmatrix lane->row/col mapping (verified in R14 at 64x32):
//   A x4 groups: (row+0,k0) (row+8,k0) (row+0,k8) (row+8,k8)  -> a0,a1,a2,a3
//   B x4 groups: (q..q+7,k0) (q..q+7,k8) (q+8..15,k0) (q+8..15,k8)
//                -> b0[2p], b1[2p], b0[2p+1], b1[2p+1]
#define GEMM_LOOP(LDA, LDB, KTOT)                                             \
    const int arow = tid >> 2, aq = (tid & 3) * 8;   /* 32 rows x 4 chunks */ \
    const uint16_t* Ag = Abase + (size_t)(m0 + arow) * (LDA) + aq;            \
    const uint16_t* Bg = Bbase + (size_t)(n0 + arow) * (LDB) + aq;            \
    _Pragma("unroll")                                                         \
    for (int j = 0; j < 4; j++) {                                             \
        *(uint4*)&Ash[0][arow + 32 * j][aq] =                                 \
            *(const uint4*)(Ag + (size_t)(32 * j) * (LDA));                   \
        *(uint4*)&Bsh[0][arow + 32 * j][aq] =                                 \
            *(const uint4*)(Bg + (size_t)(32 * j) * (LDB));                   \
    }                                                                         \
    const uint32_t aB32 = smem_u32(&Ash[0][0][0]) +                           \
        (uint32_t)((((lane & 7) + ((lane >> 3) & 1) * 8 + wm * 64) * LDHH +   \
                    (lane >> 4) * 8) * 2);                                    \
    const uint32_t bB32 = smem_u32(&Bsh[0][0][0]) +                           \
        (uint32_t)((((lane & 7) + (lane >> 4) * 8 + wn * 64) * LDHH +         \
                    ((lane >> 3) & 1) * 8) * 2);                              \
    __syncthreads();                                                          \
    const int NC = (KTOT) / 32;                                               \
    uint4 pa0, pa1, pa2, pa3, pb0, pb1, pb2, pb3;                             \
    for (int c = 0; c < NC; c++) {                                            \
        const int s = c & 1;                                                  \
        if (c + 1 < NC) {                                                     \
            const uint16_t* Ap = Ag + (size_t)(c + 1) * 32;                   \
            const uint16_t* Bp = Bg + (size_t)(c + 1) * 32;                   \
            pa0 = *(const uint4*)(Ap);                                        \
            pa1 = *(const uint4*)(Ap + (size_t)32 * (LDA));                   \
            pa2 = *(const uint4*)(Ap + (size_t)64 * (LDA));                   \
            pa3 = *(const uint4*)(Ap + (size_t)96 * (LDA));                   \
            pb0 = *(const uint4*)(Bp);                                        \
            pb1 = *(const uint4*)(Bp + (size_t)32 * (LDB));                   \
            pb2 = *(const uint4*)(Bp + (size_t)64 * (LDB));                   \
            pb3 = *(const uint4*)(Bp + (size_t)96 * (LDB));                   \
        }                                                                     \
        const uint32_t sOff = (uint32_t)s * STAGEB;                           \
        _Pragma("unroll")                                                     \
        for (int kk = 0; kk < 2; kk++) {                                      \
            uint32_t a0[4], a1[4], a2[4], a3[4];                              \
            _Pragma("unroll")                                                 \
            for (int mt = 0; mt < 4; mt++)                                    \
                LDSM_X4(a0[mt], a1[mt], a2[mt], a3[mt],                       \
                        aB32 + sOff + (uint32_t)((mt * 16 * LDHH + kk * 16) * 2)); \
            uint32_t b0[8], b1[8];                                            \
            _Pragma("unroll")                                                 \
            for (int p = 0; p < 4; p++)                                       \
                LDSM_X4(b0[2 * p], b1[2 * p], b0[2 * p + 1], b1[2 * p + 1],   \
                        bB32 + sOff + (uint32_t)((p * 16 * LDHH + kk * 16) * 2)); \
            _Pragma("unroll")                                                 \
            for (int nt = 0; nt < 8; nt++)                                    \
                _Pragma("unroll")                                             \
                for (int mt = 0; mt < 4; mt++)                                \
                    MMA_F16(acc[mt][nt][0], acc[mt][nt][1],                   \
                            acc[mt][nt][2], acc[mt][nt][3],                   \
                            a0[mt], a1[mt], a2[mt], a3[mt], b0[nt], b1[nt]);  \
        }                                                                     \
        if (c + 1 < NC) {                                                     \
            const int ns = 1 - s;                                             \
            *(uint4*)&Ash[ns][arow][aq]      = pa0;                           \
            *(uint4*)&Ash[ns][arow + 32][aq] = pa1;                           \
            *(uint4*)&Ash[ns][arow + 64][aq] = pa2;                           \
            *(uint4*)&Ash[ns][arow + 96][aq] = pa3;                           \
            *(uint4*)&Bsh[ns][arow][aq]      = pb0;                           \
            *(uint4*)&Bsh[ns][arow + 32][aq] = pb1;                           \
            *(uint4*)&Bsh[ns][arow + 64][aq] = pb2;                           \
            *(uint4*)&Bsh[ns][arow + 96][aq] = pb3;                           \
            __syncthreads();                                                  \
        }                                                                     \
    }

// ============================================================================
// GroupNorm, transposed fp16 output: x[b,c,n] -> g_hh[b,n,c]
// ============================================================================
__global__ __launch_bounds__(512) void gn_kernel(const float* __restrict__ x,
                                                 const float* __restrict__ sc,
                                                 const float* __restrict__ bi) {
    int bg = blockIdx.x;  // b*32 + g
    int b = bg >> 5, g = bg & (NG - 1);
    const float* xg = x + (size_t)bg * CPG * NTOK;
    int tid = threadIdx.x;

    const int TOT4 = CPG * NTOK / 4;
    const float4* xp = (const float4*)xg;
    float s = 0.f, ss = 0.f;
    for (int i = tid; i < TOT4; i += 512) {
        float4 v = xp[i];
        s  += v.x + v.y + v.z + v.w;
        ss += v.x * v.x + v.y * v.y + v.z * v.z + v.w * v.w;
    }
    __shared__ float rs[16], rss[16];
    for (int o = 16; o; o >>= 1) {
        s  += __shfl_xor_sync(0xffffffffu, s, o);
        ss += __shfl_xor_sync(0xffffffffu, ss, o);
    }
    if ((tid & 31) == 0) { rs[tid >> 5] = s; rss[tid >> 5] = ss; }
    __syncthreads();
    __shared__ float mean_s, rstd_s;
    if (tid == 0) {
        float S = 0.f, SS = 0.f;
        for (int w = 0; w < 16; w++) { S += rs[w]; SS += rss[w]; }
        float inv_n = 1.0f / (float)(CPG * NTOK);
        float mean = S * inv_n;
        float var  = SS * inv_n - mean * mean;
        mean_s = mean;
        rstd_s = rsqrtf(var + 1e-6f);
    }
    __syncthreads();
    float mean = mean_s, rstd = rstd_s;

    __shared__ float a_s[CPG], b_s[CPG];
    if (tid < CPG) {
        float a = rstd * sc[g * CPG + tid];
        a_s[tid] = a;
        b_s[tid] = bi[g * CPG + tid] - mean * a;
    }
    __syncthreads();

    uint16_t* Ht = g_hh + (size_t)b * NTOK * CCH + g * CPG;
#pragma unroll
    for (int rep = 0; rep < 8; rep++) {
        int n = rep * 512 + tid;
        uint16_t* op = Ht + (size_t)n * CCH;
#pragma unroll
        for (int c = 0; c < CPG; c += 2) {
            float y0 = xg[(size_t)(c + 0) * NTOK + n] * a_s[c + 0] + b_s[c + 0];
            float y1 = xg[(size_t)(c + 1) * NTOK + n] * a_s[c + 1] + b_s[c + 1];
            uint32_t pk;
            PACK_H2(pk, y0, y1);
            *(uint32_t*)(op + c) = pk;
        }
    }
}

// ============================================================================
// Weight convert fp32 -> fp16 for all three weights. grid (256, 3).
// ============================================================================
__global__ __launch_bounds__(256) void convw_kernel(const float* __restrict__ wq,
                                                    const float* __restrict__ wk,
                                                    const float* __restrict__ wv) {
    const int sel = blockIdx.y;
    const float* w = (sel == 0) ? wq : (sel == 1) ? wk : wv;
    uint16_t* o   = (sel == 0) ? g_wq : (sel == 1) ? g_wk : g_wv;
    int i = blockIdx.x * 256 + threadIdx.x;   // float4 index, 65536 total
    float4 v = *(const float4*)(w + 4 * (size_t)i);
    uint2 pk;
    PACK_H2(pk.x, v.x, v.y);
    PACK_H2(pk.y, v.z, v.w);
    *(uint2*)(o + 4 * (size_t)i) = pk;
}

// ============================================================================
// Q/K projection: Out[n][o] = H[n][:]·W[o][:] + bias[o], fp16 out.
// grid (CCH/128=4, NTOK/128=32, 16): z = b*2 + sel. 128 threads.
// ============================================================================
__global__ __launch_bounds__(128) void qkproj_kernel(
    const float* __restrict__ bq, const float* __restrict__ bk) {
    __shared__ uint16_t Ash[2][128][LDHH];
    __shared__ uint16_t Bsh[2][128][LDHH];
    const int z = blockIdx.z;
    const int b = z >> 1, sel = z & 1;
    const uint16_t* Abase = g_hh + (size_t)b * SBN;
    const uint16_t* Bbase = sel ? g_wk : g_wq;
    const float* bias = sel ? bk : bq;
    uint16_t* Ob = (sel ? g_kt : g_qt) + (size_t)b * SBN;
    const int m0 = blockIdx.y * 128, n0 = blockIdx.x * 128;
    DECL_ACC();
    GEMM_LOOP(CCH, CCH, CCH);

#pragma unroll
    for (int mt = 0; mt < 4; mt++) {
        const int r0 = m0 + wm * 64 + mt * 16 + g;
        const int r1 = r0 + 8;
#pragma unroll
        for (int nt = 0; nt < 8; nt++) {
            const int col = n0 + wn * 64 + nt * 8 + 2 * t;
            float c0 = bias[col], c1 = bias[col + 1];
            uint32_t p0, p1;
            PACK_H2(p0, acc[mt][nt][0] + c0, acc[mt][nt][1] + c1);
            PACK_H2(p1, acc[mt][nt][2] + c0, acc[mt][nt][3] + c1);
            *(uint32_t*)(Ob + (size_t)r0 * CCH + col) = p0;
            *(uint32_t*)(Ob + (size_t)r1 * CCH + col) = p1;
        }
    }
}

// ============================================================================
// V projection: g_v[b][o][n] = Wv[o][:]·H[n][:] + bv[o], fp16 out.
// grid (NTOK/128=32, CCH/128=4, 8), 128 threads
// ============================================================================
__global__ __launch_bounds__(128) void vproj_kernel(const float* __restrict__ bv) {
    __shared__ uint16_t Ash[2][128][LDHH];
    __shared__ uint16_t Bsh[2][128][LDHH];
    const int b = blockIdx.z;
    const uint16_t* Abase = g_wv;
    const uint16_t* Bbase = g_hh + (size_t)b * SBN;
    uint16_t* Ob = g_v + (size_t)b * SBN;
    const int m0 = blockIdx.y * 128, n0 = blockIdx.x * 128;
    DECL_ACC();
    GEMM_LOOP(CCH, CCH, CCH);

#pragma unroll
    for (int mt = 0; mt < 4; mt++) {
        const int r0 = m0 + wm * 64 + mt * 16 + g;
        const int r1 = r0 + 8;
        const float rb0 = bv[r0], rb1 = bv[r1];
#pragma unroll
        for (int nt = 0; nt < 8; nt++) {
            const int col = n0 + wn * 64 + nt * 8 + 2 * t;
            uint32_t p0, p1;
            PACK_H2(p0, acc[mt][nt][0] + rb0, acc[mt][nt][1] + rb0);
            PACK_H2(p1, acc[mt][nt][2] + rb1, acc[mt][nt][3] + rb1);
            *(uint32_t*)(Ob + (size_t)r0 * NTOK + col) = p0;
            *(uint32_t*)(Ob + (size_t)r1 * NTOK + col) = p1;
        }
    }
}

// ============================================================================
// S[i][j] = scale * Qt[i][:]·Kt[j][:], fp32 out. grid (32, 32, 8), 128 thr
// ============================================================================
__global__ __launch_bounds__(128) void s_kernel() {
    __shared__ uint16_t Ash[2][128][LDHH];
    __shared__ uint16_t Bsh[2][128][LDHH];
    const int b = blockIdx.z;
    const uint16_t* Abase = g_qt + (size_t)b * SBN;
    const uint16_t* Bbase = g_kt + (size_t)b * SBN;
    float* Sb = g_s + (size_t)b * SBS;
    const int m0 = blockIdx.y * 128, n0 = blockIdx.x * 128;
    DECL_ACC();
    GEMM_LOOP(CCH, CCH, CCH);

    const float scale = 0.044194173824159216f;  // 512^-0.5
#pragma unroll
    for (int mt = 0; mt < 4; mt++) {
        const int r0 = m0 + wm * 64 + mt * 16 + g;
        const int r1 = r0 + 8;
#pragma unroll
        for (int nt = 0; nt < 8; nt++) {
            const int col = n0 + wn * 64 + nt * 8 + 2 * t;
            float2 lo = { acc[mt][nt][0] * scale, acc[mt][nt][1] * scale };
            float2 hi = { acc[mt][nt][2] * scale, acc[mt][nt][3] * scale };
            *(float2*)(Sb + (size_t)r0 * NTOK + col) = lo;
            *(float2*)(Sb + (size_t)r1 * NTOK + col) = hi;
        }
    }
}

// ============================================================================
// Row softmax: read g_s fp32, write g_p fp16. One block per row.
// ============================================================================
__global__ __launch_bounds__(256) void softmax_kernel() {
    size_t row = blockIdx.x;
    const float4* p = (const float4*)(g_s + row * NTOK);
    uint16_t* ph = g_p + row * NTOK;
    int tid = threadIdx.x;

    float4 v[4];
    float m = -1e30f;
#pragma unroll
    for (int i = 0; i < 4; i++) {
        v[i] = p[tid + 256 * i];
        m = fmaxf(m, fmaxf(fmaxf(v[i].x, v[i].y), fmaxf(v[i].z, v[i].w)));
    }
    __shared__ float redm[8], reds[8];
    for (int o = 16; o; o >>= 1) m = fmaxf(m, __shfl_xor_sync(0xffffffffu, m, o));
    if ((tid & 31) == 0) redm[tid >> 5] = m;
    __syncthreads();
    float M = redm[0];
#pragma unroll
    for (int w = 1; w < 8; w++) M = fmaxf(M, redm[w]);

    float s = 0.f;
#pragma unroll
    for (int i = 0; i < 4; i++) {
        v[i].x = __expf(v[i].x - M); v[i].y = __expf(v[i].y - M);
        v[i].z = __expf(v[i].z - M); v[i].w = __expf(v[i].w - M);
        s += v[i].x + v[i].y + v[i].z + v[i].w;
    }
    for (int o = 16; o; o >>= 1) s += __shfl_xor_sync(0xffffffffu, s, o);
    if ((tid & 31) == 0) reds[tid >> 5] = s;
    __syncthreads();
    float S = 0.f;
#pragma unroll
    for (int w = 0; w < 8; w++) S += reds[w];
    float inv = 1.0f / S;
#pragma unroll
    for (int i = 0; i < 4; i++) {
        int idx = (tid + 256 * i) * 4;
        uint2 pk;
        PACK_H2(pk.x, v[i].x * inv, v[i].y * inv);
        PACK_H2(pk.y, v[i].z * inv, v[i].w * inv);
        *(uint2*)(ph + idx) = pk;
    }
}

// ============================================================================
// out[c][i] = x[c][i] + V[c][:]·P[i][:], fp32 out. grid (32, 4, 8), 128 thr
// ============================================================================
__global__ __launch_bounds__(128) void pv_kernel(const float* __restrict__ x,
                                                 float* __restrict__ out) {
    __shared__ uint16_t Ash[2][128][LDHH];
    __shared__ uint16_t Bsh[2][128][LDHH];
    const int b = blockIdx.z;
    const uint16_t* Abase = g_v + (size_t)b * SBN;
    const uint16_t* Bbase = g_p + (size_t)b * SBS;
    const size_t dbase = (size_t)b * SBN;
    const int m0 = blockIdx.y * 128, n0 = blockIdx.x * 128;
    DECL_ACC();
    GEMM_LOOP(NTOK, NTOK, NTOK);

#pragma unroll
    for (int mt = 0; mt < 4; mt++) {
        const int r0 = m0 + wm * 64 + mt * 16 + g;
        const int r1 = r0 + 8;
#pragma unroll
        for (int nt = 0; nt < 8; nt++) {
            const int col = n0 + wn * 64 + nt * 8 + 2 * t;
            size_t o0 = dbase + (size_t)r0 * NTOK + col;
            size_t o1 = dbase + (size_t)r1 * NTOK + col;
            float2 x0 = *(const float2*)(x + o0);
            float2 x1 = *(const float2*)(x + o1);
            float2 lo = { acc[mt][nt][0] + x0.x, acc[mt][nt][1] + x0.y };
            float2 hi = { acc[mt][nt][2] + x1.x, acc[mt][nt][3] + x1.y };
            *(float2*)(out + o0) = lo;
            *(float2*)(out + o1) = hi;
        }
    }
}

// ============================================================================
extern "C" void kernel_launch(void* const* d_in, const int* in_sizes, int n_in,
                              void* d_out, int out_size) {
    const float* x   = (const float*)d_in[0];
    const float* gns = (const float*)d_in[1];
    const float* gnb = (const float*)d_in[2];
    const float* wq  = (const float*)d_in[3];
    const float* bq  = (const float*)d_in[4];
    const float* wk  = (const float*)d_in[5];
    const float* bk  = (const float*)d_in[6];
    const float* wv  = (const float*)d_in[7];
    const float* bv  = (const float*)d_in[8];
    float* out = (float*)d_out;
    (void)in_sizes; (void)n_in; (void)out_size;

    gn_kernel<<<BATCH * NG, 512>>>(x, gns, gnb);
    convw_kernel<<<dim3(256, 3), 256>>>(wq, wk, wv);

    qkproj_kernel<<<dim3(CCH / 128, NTOK / 128, BATCH * 2), 128>>>(bq, bk);
    vproj_kernel<<<dim3(NTOK / 128, CCH / 128, BATCH), 128>>>(bv);
    s_kernel<<<dim3(NTOK / 128, NTOK / 128, BATCH), 128>>>();
    softmax_kernel<<<BATCH * NTOK, 256>>>();
    pv_kernel<<<dim3(NTOK / 128, CCH / 128, BATCH), 128>>>(x, out);
}

// round 16
// speedup vs baseline: 1.1604x; 1.1604x over previous
#include <cuda_runtime.h>
#include <cstdint>
#include <math.h>

#define CCH   512
#define NTOK  4096
#define BATCH 8
#define NG    32
#define CPG   16

#define SBN ((size_t)NTOK * CCH)    // per-batch activation stride (elements)
#define SBS ((size_t)NTOK * NTOK)   // per-batch attention stride

// -------- scratch (device globals; referenced ONLY in device code) --------
__device__ __align__(16) uint16_t g_hh[(size_t)BATCH * NTOK * CCH];  // GN out, TRANSPOSED [b][n][c]
__device__ __align__(16) uint16_t g_qt[(size_t)BATCH * NTOK * CCH];  // Qt [b][n][c]
__device__ __align__(16) uint16_t g_kt[(size_t)BATCH * NTOK * CCH];  // Kt [b][n][c]
__device__ __align__(16) uint16_t g_v [(size_t)BATCH * CCH * NTOK];  // V  [b][c][n]
__device__ __align__(16) uint16_t g_wq[CCH * CCH];
__device__ __align__(16) uint16_t g_wk[CCH * CCH];
__device__ __align__(16) uint16_t g_wv[CCH * CCH];
__device__ float g_s[(size_t)BATCH * NTOK * NTOK];                   // logits fp32 [b][i][j]
__device__ __align__(16) uint16_t g_p[(size_t)BATCH * NTOK * NTOK]; // probs fp16 [b][i][j]

// pack two fp32 -> one fp16x2 word (lo = first arg, hi = second arg)
#define PACK_H2(dst, lo, hi)                                                  \
    asm("cvt.rn.f16x2.f32 %0, %1, %2;" : "=r"(dst) : "f"(hi), "f"(lo))

#define MMA_F16(c0, c1, c2, c3, a0, a1, a2, a3, b0, b1)                       \
    asm volatile("mma.sync.aligned.m16n8k16.row.col.f32.f16.f16.f32 "         \
                 "{%0,%1,%2,%3}, {%4,%5,%6,%7}, {%8,%9}, {%0,%1,%2,%3};"      \
                 : "+f"(c0), "+f"(c1), "+f"(c2), "+f"(c3)                     \
                 : "r"(a0), "r"(a1), "r"(a2), "r"(a3), "r"(b0), "r"(b1))

#define LDSM_X4(r0, r1, r2, r3, addr)                                         \
    asm volatile("ldmatrix.sync.aligned.m8n8.x4.shared.b16 {%0,%1,%2,%3}, [%4];" \
                 : "=r"(r0), "=r"(r1), "=r"(r2), "=r"(r3) : "r"(addr))

#define CP16(sa, gp) asm volatile("cp.async.cg.shared.global [%0], [%1], 16;" :: "r"(sa), "l"(gp))
#define CP_COMMIT()  asm volatile("cp.async.commit_group;" ::: "memory")
#define CP_WAIT0()   asm volatile("cp.async.wait_group 0;" ::: "memory")

__device__ __forceinline__ uint32_t smem_u32(const void* p) {
    uint32_t a;
    asm("{ .reg .u64 t; cvta.to.shared.u64 t, %1; cvt.u32.u64 %0, t; }" : "=r"(a) : "l"(p));
    return a;
}

// ============================================================================
// Shared GEMM machinery: CTA 128x128x32(halves), 256 threads (2x4 warps),
// warp tile 64x32. Double-buffered static smem [2][128][40] uint16,
// cp.async staging (one group ahead), one __syncthreads per slab,
// fragments via ldmatrix.x4.   D[m][n] = sum_k A[m+m0][k] * B[n+n0][k]
// ============================================================================
#define LDHH 40                       // padded smem row (halves)
#define STAGEB (128 * LDHH * 2)       // stage stride in bytes = 10240

#define DECL_ACC()                                                            \
    const int tid = threadIdx.x;                                              \
    const int wid = tid >> 5, lane = tid & 31;                                \
    const int wm = wid & 1, wn = wid >> 1;      /* 2 (M) x 4 (N) warps */     \
    const int g = lane >> 2, t = lane & 3;                                    \
    float acc[4][4][4];                                                       \
    _Pragma("unroll")                                                         \
    for (int mt = 0; mt < 4; mt++)                                            \
        _Pragma("unroll")                                                     \
        for (int nt = 0; nt < 4; nt++) {                                      \
            acc[mt][nt][0] = 0.f; acc[mt][nt][1] = 0.f;                       \
            acc[mt][nt][2] = 0.f; acc[mt][nt][3] = 0.f;                       \
        }

// ldmatrix lane->row/col mapping (verified in R14):
//   A x4 groups: (row+0,k0) (row+8,k0) (row+0,k8) (row+8,k8)  -> a0,a1,a2,a3
//   B x4 groups: (nt0,k0) (nt0,k8) (nt0+1,k0) (nt0+1,k8)      -> b0,b1,b0',b1'
#define GEMM_LOOP(LDA, LDB, KTOT)                                             \
    const int arow = tid >> 2, aq = (tid & 3) * 8;   /* 64 rows x 4 chunks */ \
    const uint16_t* Ag = Abase + (size_t)(m0 + arow) * (LDA) + aq;            \
    const uint16_t* Bg = Bbase + (size_t)(n0 + arow) * (LDB) + aq;            \
    const uint32_t aSt = smem_u32(&Ash[0][arow][aq]);                         \
    const uint32_t bSt = smem_u32(&Bsh[0][arow][aq]);                         \
    CP16(aSt, Ag);                                                            \
    CP16(aSt + 64 * LDHH * 2, Ag + (size_t)64 * (LDA));                       \
    CP16(bSt, Bg);                                                            \
    CP16(bSt + 64 * LDHH * 2, Bg + (size_t)64 * (LDB));                       \
    CP_COMMIT();                                                              \
    const uint32_t aB32 = smem_u32(&Ash[0][0][0]) +                           \
        (uint32_t)((((lane & 7) + ((lane >> 3) & 1) * 8 + wm * 64) * LDHH +   \
                    (lane >> 4) * 8) * 2);                                    \
    const uint32_t bB32 = smem_u32(&Bsh[0][0][0]) +                           \
        (uint32_t)((((lane & 7) + (lane >> 4) * 8 + wn * 32) * LDHH +         \
                    ((lane >> 3) & 1) * 8) * 2);                              \
    const int NC = (KTOT) / 32;                                               \
    for (int c = 0; c < NC; c++) {                                            \
        CP_WAIT0();                                                           \
        __syncthreads();                                                      \
        if (c + 1 < NC) {                                                     \
            const uint16_t* Ap = Ag + (size_t)(c + 1) * 32;                   \
            const uint16_t* Bp = Bg + (size_t)(c + 1) * 32;                   \
            const uint32_t off = (uint32_t)((c + 1) & 1) * STAGEB;            \
            CP16(aSt + off, Ap);                                              \
            CP16(aSt + off + 64 * LDHH * 2, Ap + (size_t)64 * (LDA));         \
            CP16(bSt + off, Bp);                                              \
            CP16(bSt + off + 64 * LDHH * 2, Bp + (size_t)64 * (LDB));         \
            CP_COMMIT();                                                      \
        }                                                                     \
        const uint32_t sOff = (uint32_t)(c & 1) * STAGEB;                     \
        _Pragma("unroll")                                                     \
        for (int kk = 0; kk < 2; kk++) {                                      \
            uint32_t a0[4], a1[4], a2[4], a3[4];                              \
            _Pragma("unroll")                                                 \
            for (int mt = 0; mt < 4; mt++)                                    \
                LDSM_X4(a0[mt], a1[mt], a2[mt], a3[mt],                       \
                        aB32 + sOff + (uint32_t)((mt * 16 * LDHH + kk * 16) * 2)); \
            uint32_t b0[4], b1[4];                                            \
            LDSM_X4(b0[0], b1[0], b0[1], b1[1],                               \
                    bB32 + sOff + (uint32_t)((kk * 16) * 2));                 \
            LDSM_X4(b0[2], b1[2], b0[3], b1[3],                               \
                    bB32 + sOff + (uint32_t)((16 * LDHH + kk * 16) * 2));     \
            _Pragma("unroll")                                                 \
            for (int nt = 0; nt < 4; nt++)                                    \
                _Pragma("unroll")                                             \
                for (int mt = 0; mt < 4; mt++)                                \
                    MMA_F16(acc[mt][nt][0], acc[mt][nt][1],                   \
                            acc[mt][nt][2], acc[mt][nt][3],                   \
                            a0[mt], a1[mt], a2[mt], a3[mt], b0[nt], b1[nt]);  \
        }                                                                     \
    }

// ============================================================================
// GroupNorm, transposed fp16 output: x[b,c,n] -> g_hh[b,n,c]
// ============================================================================
__global__ __launch_bounds__(512) void gn_kernel(const float* __restrict__ x,
                                                 const float* __restrict__ sc,
                                                 const float* __restrict__ bi) {
    int bg = blockIdx.x;  // b*32 + g
    int b = bg >> 5, g = bg & (NG - 1);
    const float* xg = x + (size_t)bg * CPG * NTOK;
    int tid = threadIdx.x;

    const int TOT4 = CPG * NTOK / 4;
    const float4* xp = (const float4*)xg;
    float s = 0.f, ss = 0.f;
    for (int i = tid; i < TOT4; i += 512) {
        float4 v = xp[i];
        s  += v.x + v.y + v.z + v.w;
        ss += v.x * v.x + v.y * v.y + v.z * v.z + v.w * v.w;
    }
    __shared__ float rs[16], rss[16];
    for (int o = 16; o; o >>= 1) {
        s  += __shfl_xor_sync(0xffffffffu, s, o);
        ss += __shfl_xor_sync(0xffffffffu, ss, o);
    }
    if ((tid & 31) == 0) { rs[tid >> 5] = s; rss[tid >> 5] = ss; }
    __syncthreads();
    __shared__ float mean_s, rstd_s;
    if (tid == 0) {
        float S = 0.f, SS = 0.f;
        for (int w = 0; w < 16; w++) { S += rs[w]; SS += rss[w]; }
        float inv_n = 1.0f / (float)(CPG * NTOK);
        float mean = S * inv_n;
        float var  = SS * inv_n - mean * mean;
        mean_s = mean;
        rstd_s = rsqrtf(var + 1e-6f);
    }
    __syncthreads();
    float mean = mean_s, rstd = rstd_s;

    __shared__ float a_s[CPG], b_s[CPG];
    if (tid < CPG) {
        float a = rstd * sc[g * CPG + tid];
        a_s[tid] = a;
        b_s[tid] = bi[g * CPG + tid] - mean * a;
    }
    __syncthreads();

    uint16_t* Ht = g_hh + (size_t)b * NTOK * CCH + g * CPG;
#pragma unroll
    for (int rep = 0; rep < 8; rep++) {
        int n = rep * 512 + tid;
        uint16_t* op = Ht + (size_t)n * CCH;
#pragma unroll
        for (int c = 0; c < CPG; c += 2) {
            float y0 = xg[(size_t)(c + 0) * NTOK + n] * a_s[c + 0] + b_s[c + 0];
            float y1 = xg[(size_t)(c + 1) * NTOK + n] * a_s[c + 1] + b_s[c + 1];
            uint32_t pk;
            PACK_H2(pk, y0, y1);
            *(uint32_t*)(op + c) = pk;
        }
    }
}

// ============================================================================
// Weight convert fp32 -> fp16 for all three weights. grid (256, 3).
// ============================================================================
__global__ __launch_bounds__(256) void convw_kernel(const float* __restrict__ wq,
                                                    const float* __restrict__ wk,
                                                    const float* __restrict__ wv) {
    const int sel = blockIdx.y;
    const float* w = (sel == 0) ? wq : (sel == 1) ? wk : wv;
    uint16_t* o   = (sel == 0) ? g_wq : (sel == 1) ? g_wk : g_wv;
    int i = blockIdx.x * 256 + threadIdx.x;   // float4 index, 65536 total
    float4 v = *(const float4*)(w + 4 * (size_t)i);
    uint2 pk;
    PACK_H2(pk.x, v.x, v.y);
    PACK_H2(pk.y, v.z, v.w);
    *(uint2*)(o + 4 * (size_t)i) = pk;
}

// ============================================================================
// Q/K projection: Out[n][o] = H[n][:]·W[o][:] + bias[o], fp16 out.
// grid (CCH/128=4, NTOK/128=32, 16): z = b*2 + sel.
// ============================================================================
__global__ __launch_bounds__(256) void qkproj_kernel(
    const float* __restrict__ bq, const float* __restrict__ bk) {
    __shared__ uint16_t Ash[2][128][LDHH];
    __shared__ uint16_t Bsh[2][128][LDHH];
    const int z = blockIdx.z;
    const int b = z >> 1, sel = z & 1;
    const uint16_t* Abase = g_hh + (size_t)b * SBN;
    const uint16_t* Bbase = sel ? g_wk : g_wq;
    const float* bias = sel ? bk : bq;
    uint16_t* Ob = (sel ? g_kt : g_qt) + (size_t)b * SBN;
    const int m0 = blockIdx.y * 128, n0 = blockIdx.x * 128;
    DECL_ACC();
    GEMM_LOOP(CCH, CCH, CCH);

#pragma unroll
    for (int mt = 0; mt < 4; mt++) {
        const int r0 = m0 + wm * 64 + mt * 16 + g;
        const int r1 = r0 + 8;
#pragma unroll
        for (int nt = 0; nt < 4; nt++) {
            const int col = n0 + wn * 32 + nt * 8 + 2 * t;
            float c0 = bias[col], c1 = bias[col + 1];
            uint32_t p0, p1;
            PACK_H2(p0, acc[mt][nt][0] + c0, acc[mt][nt][1] + c1);
            PACK_H2(p1, acc[mt][nt][2] + c0, acc[mt][nt][3] + c1);
            *(uint32_t*)(Ob + (size_t)r0 * CCH + col) = p0;
            *(uint32_t*)(Ob + (size_t)r1 * CCH + col) = p1;
        }
    }
}

// ============================================================================
// V projection: g_v[b][o][n] = Wv[o][:]·H[n][:] + bv[o], fp16 out.
// grid (NTOK/128=32, CCH/128=4, 8)
// ============================================================================
__global__ __launch_bounds__(256) void vproj_kernel(const float* __restrict__ bv) {
    __shared__ uint16_t Ash[2][128][LDHH];
    __shared__ uint16_t Bsh[2][128][LDHH];
    const int b = blockIdx.z;
    const uint16_t* Abase = g_wv;
    const uint16_t* Bbase = g_hh + (size_t)b * SBN;
    uint16_t* Ob = g_v + (size_t)b * SBN;
    const int m0 = blockIdx.y * 128, n0 = blockIdx.x * 128;
    DECL_ACC();
    GEMM_LOOP(CCH, CCH, CCH);

#pragma unroll
    for (int mt = 0; mt < 4; mt++) {
        const int r0 = m0 + wm * 64 + mt * 16 + g;
        const int r1 = r0 + 8;
        const float rb0 = bv[r0], rb1 = bv[r1];
#pragma unroll
        for (int nt = 0; nt < 4; nt++) {
            const int col = n0 + wn * 32 + nt * 8 + 2 * t;
            uint32_t p0, p1;
            PACK_H2(p0, acc[mt][nt][0] + rb0, acc[mt][nt][1] + rb0);
            PACK_H2(p1, acc[mt][nt][2] + rb1, acc[mt][nt][3] + rb1);
            *(uint32_t*)(Ob + (size_t)r0 * NTOK + col) = p0;
            *(uint32_t*)(Ob + (size_t)r1 * NTOK + col) = p1;
        }
    }
}

// ============================================================================
// S[i][j] = scale * Qt[i][:]·Kt[j][:], fp32 out. grid (32, 32, 8)
// ============================================================================
__global__ __launch_bounds__(256) void s_kernel() {
    __shared__ uint16_t Ash[2][128][LDHH];
    __shared__ uint16_t Bsh[2][128][LDHH];
    const int b = blockIdx.z;
    const uint16_t* Abase = g_qt + (size_t)b * SBN;
    const uint16_t* Bbase = g_kt + (size_t)b * SBN;
    float* Sb = g_s + (size_t)b * SBS;
    const int m0 = blockIdx.y * 128, n0 = blockIdx.x * 128;
    DECL_ACC();
    GEMM_LOOP(CCH, CCH, CCH);

    const float scale = 0.044194173824159216f;  // 512^-0.5
#pragma unroll
    for (int mt = 0; mt < 4; mt++) {
        const int r0 = m0 + wm * 64 + mt * 16 + g;
        const int r1 = r0 + 8;
#pragma unroll
        for (int nt = 0; nt < 4; nt++) {
            const int col = n0 + wn * 32 + nt * 8 + 2 * t;
            float2 lo = { acc[mt][nt][0] * scale, acc[mt][nt][1] * scale };
            float2 hi = { acc[mt][nt][2] * scale, acc[mt][nt][3] * scale };
            *(float2*)(Sb + (size_t)r0 * NTOK + col) = lo;
            *(float2*)(Sb + (size_t)r1 * NTOK + col) = hi;
        }
    }
}

// ============================================================================
// Row softmax: read g_s fp32, write g_p fp16. One block per row.
// ============================================================================
__global__ __launch_bounds__(256) void softmax_kernel() {
    size_t row = blockIdx.x;
    const float4* p = (const float4*)(g_s + row * NTOK);
    uint16_t* ph = g_p + row * NTOK;
    int tid = threadIdx.x;

    float4 v[4];
    float m = -1e30f;
#pragma unroll
    for (int i = 0; i < 4; i++) {
        v[i] = p[tid + 256 * i];
        m = fmaxf(m, fmaxf(fmaxf(v[i].x, v[i].y), fmaxf(v[i].z, v[i].w)));
    }
    __shared__ float redm[8], reds[8];
    for (int o = 16; o; o >>= 1) m = fmaxf(m, __shfl_xor_sync(0xffffffffu, m, o));
    if ((tid & 31) == 0) redm[tid >> 5] = m;
    __syncthreads();
    float M = redm[0];
#pragma unroll
    for (int w = 1; w < 8; w++) M = fmaxf(M, redm[w]);

    float s = 0.f;
#pragma unroll
    for (int i = 0; i < 4; i++) {
        v[i].x = __expf(v[i].x - M); v[i].y = __expf(v[i].y - M);
        v[i].z = __expf(v[i].z - M); v[i].w = __expf(v[i].w - M);
        s += v[i].x + v[i].y + v[i].z + v[i].w;
    }
    for (int o = 16; o; o >>= 1) s += __shfl_xor_sync(0xffffffffu, s, o);
    if ((tid & 31) == 0) reds[tid >> 5] = s;
    __syncthreads();
    float S = 0.f;
#pragma unroll
    for (int w = 0; w < 8; w++) S += reds[w];
    float inv = 1.0f / S;
#pragma unroll
    for (int i = 0; i < 4; i++) {
        int idx = (tid + 256 * i) * 4;
        uint2 pk;
        PACK_H2(pk.x, v[i].x * inv, v[i].y * inv);
        PACK_H2(pk.y, v[i].z * inv, v[i].w * inv);
        *(uint2*)(ph + idx) = pk;
    }
}

// ============================================================================
// out[c][i] = x[c][i] + V[c][:]·P[i][:], fp32 out. grid (32, 4, 8)
// ============================================================================
__global__ __launch_bounds__(256) void pv_kernel(const float* __restrict__ x,
                                                 float* __restrict__ out) {
    __shared__ uint16_t Ash[2][128][LDHH];
    __shared__ uint16_t Bsh[2][128][LDHH];
    const int b = blockIdx.z;
    const uint16_t* Abase = g_v + (size_t)b * SBN;
    const uint16_t* Bbase = g_p + (size_t)b * SBS;
    const size_t dbase = (size_t)b * SBN;
    const int m0 = blockIdx.y * 128, n0 = blockIdx.x * 128;
    DECL_ACC();
    GEMM_LOOP(NTOK, NTOK, NTOK);

#pragma unroll
    for (int mt = 0; mt < 4; mt++) {
        const int r0 = m0 + wm * 64 + mt * 16 + g;
        const int r1 = r0 + 8;
#pragma unroll
        for (int nt = 0; nt < 4; nt++) {
            const int col = n0 + wn * 32 + nt * 8 + 2 * t;
            size_t o0 = dbase + (size_t)r0 * NTOK + col;
            size_t o1 = dbase + (size_t)r1 * NTOK + col;
            float2 x0 = *(const float2*)(x + o0);
            float2 x1 = *(const float2*)(x + o1);
            float2 lo = { acc[mt][nt][0] + x0.x, acc[mt][nt][1] + x0.y };
            float2 hi = { acc[mt][nt][2] + x1.x, acc[mt][nt][3] + x1.y };
            *(float2*)(out + o0) = lo;
            *(float2*)(out + o1) = hi;
        }
    }
}

// ============================================================================
extern "C" void kernel_launch(void* const* d_in, const int* in_sizes, int n_in,
                              void* d_out, int out_size) {
    const float* x   = (const float*)d_in[0];
    const float* gns = (const float*)d_in[1];
    const float* gnb = (const float*)d_in[2];
    const float* wq  = (const float*)d_in[3];
    const float* bq  = (const float*)d_in[4];
    const float* wk  = (const float*)d_in[5];
    const float* bk  = (const float*)d_in[6];
    const float* wv  = (const float*)d_in[7];
    const float* bv  = (const float*)d_in[8];
    float* out = (float*)d_out;
    (void)in_sizes; (void)n_in; (void)out_size;

    gn_kernel<<<BATCH * NG, 512>>>(x, gns, gnb);
    convw_kernel<<<dim3(256, 3), 256>>>(wq, wk, wv);

    qkproj_kernel<<<dim3(CCH / 128, NTOK / 128, BATCH * 2), 256>>>(bq, bk);
    vproj_kernel<<<dim3(NTOK / 128, CCH / 128, BATCH), 256>>>(bv);
    s_kernel<<<dim3(NTOK / 128, NTOK / 128, BATCH), 256>>>();
    softmax_kernel<<<BATCH * NTOK, 256>>>();
    pv_kernel<<<dim3(NTOK / 128, CCH / 128, BATCH), 256>>>(x, out);
}